// round 14
// baseline (speedup 1.0000x reference)
#include <cuda_runtime.h>
#include <math.h>

#define BB 8
#define LL 512
#define DD 128
#define UU 32
#define EPSF 1e-7f
#define NC 64            // 8-row chunks per batch
#define NSC 8            // superchunks of 64 rows per batch

// scratch (no allocs allowed)
__device__ float g_qs[BB*LL];
__device__ float g_ks[BB*LL];
__device__ float g_ek[BB*LL];
__device__ float g_T8 [BB*NC*DD];       // 8-row sums of x
__device__ float g_T8e[BB*NC*DD];       // 8-row sums of ek*x
__device__ float g_SO0[BB*(NSC+1)*DD];  // exclusive superchunk offsets of x; [8]=total
__device__ float g_SO1[BB*(NSC+1)*DD];  // exclusive superchunk offsets of ek*x
__device__ float g_A[BB*LL];            // exp(qc-m)/Z
__device__ float g_E[BB*LL];            // exp(-m)/Z

// ---------------------------------------------------------------------------
// K1: register weight fold with SMEM partial reduction (no fold shuffles) +
//     warp-per-token scalars + chunk-8 sums. grid=512, blk=256
// ---------------------------------------------------------------------------
__global__ __launch_bounds__(256)
void k1(const float* __restrict__ x,
        const float* __restrict__ Wt, const float* __restrict__ Wx,
        const float* __restrict__ Wa) {
    int tid  = threadIdx.x;
    int warp = tid >> 5;
    int lane = tid & 31;
    int token = blockIdx.x * 8 + warp;          // 8 consecutive rows, same batch

    __shared__ __align__(16) float swt[DD], swx[DD];
    __shared__ __align__(16) float srow[8*DD];
    __shared__ float psA[DD][9];                // fold partials, pad-9 (conflict-free)
    __shared__ float psB[DD][9];
    __shared__ float sek[8];

    // issue x load first (long latency, overlaps fold)
    const float4* xr = reinterpret_cast<const float4*>(x + (size_t)token * DD);
    float4 xv = xr[lane];
    reinterpret_cast<float4*>(srow)[warp*32 + lane] = xv;

    // fold partials: ug = tid&7 fixed; row(i) = (tid + 256*i) >> 3.
    // Each thread writes one partial per row it touches; no shuffles.
    {
        int ug = tid & 7;
        float4 wa = reinterpret_cast<const float4*>(Wa)[ug];
        const float4* Wt4 = reinterpret_cast<const float4*>(Wt);
        const float4* Wx4 = reinterpret_cast<const float4*>(Wx);
#pragma unroll
        for (int i = 0; i < 4; i++) {
            int idx = tid + i*256;
            int row = idx >> 3;
            float4 vt = __ldg(Wt4 + idx);
            float4 vx = __ldg(Wx4 + idx);
            psA[row][ug] = vt.x*wa.x + vt.y*wa.y + vt.z*wa.z + vt.w*wa.w;
            psB[row][ug] = vx.x*wa.x + vx.y*wa.y + vx.z*wa.z + vx.w*wa.w;
        }
    }
    __syncthreads();    // guards srow AND fold partials

    // reduce partials: thread d sums 8 partials per matrix (LDS conflict-free)
    if (tid < DD) {
        float at = 0.f, ax = 0.f;
#pragma unroll
        for (int u = 0; u < 8; u++) {
            at += psA[tid][u];
            ax += psB[tid][u];
        }
        swt[tid] = at;
        swx[tid] = ax;
    }
    __syncthreads();

    float4 wt = reinterpret_cast<const float4*>(swt)[lane];
    float4 wx = reinterpret_cast<const float4*>(swx)[lane];
    float q = xv.x*wt.x + xv.y*wt.y + xv.z*wt.z + xv.w*wt.w;
    float k = xv.x*wx.x + xv.y*wx.y + xv.z*wx.z + xv.w*wx.w;
#pragma unroll
    for (int o = 16; o; o >>= 1) {
        q += __shfl_down_sync(0xFFFFFFFFu, q, o);
        k += __shfl_down_sync(0xFFFFFFFFu, k, o);
    }
    if (lane == 0) {
        float e = expf(k);
        g_qs[token] = q;
        g_ks[token] = k;
        g_ek[token] = e;
        sek[warp] = e;
    }
    __syncthreads();

    if (tid < DD) {
        int d = tid;
        float s0 = 0.f, s1 = 0.f;
#pragma unroll
        for (int w = 0; w < 8; w++) {
            float v = srow[w*DD + d];
            s0 += v;
            s1 = fmaf(sek[w], v, s1);
        }
        size_t o = (size_t)blockIdx.x * DD + d;
        g_T8 [o] = s0;
        g_T8e[o] = s1;
    }
}

// ---------------------------------------------------------------------------
// K2: per-batch: scan(ek) + window max + A/E scalars + superchunk offsets SO.
//     grid=8, blk=512
// ---------------------------------------------------------------------------
__global__ __launch_bounds__(512, 1)
void k2(const float* __restrict__ bh, const float* __restrict__ Wa,
        const float* __restrict__ ba) {
    int b   = blockIdx.x;
    int tid = threadIdx.x;

    __shared__ float sks[LL];
    __shared__ float scan[2][LL];
    __shared__ float cmax[LL/16];
    __shared__ float s8[2][NSC][DD];
    __shared__ float sc_c;

    sks[tid]     = g_ks[b*LL + tid];
    scan[0][tid] = g_ek[b*LL + tid];
    if (tid == 0) {
        float c = __ldg(ba);
#pragma unroll
        for (int u = 0; u < UU; u++) c = fmaf(__ldg(bh + u), __ldg(Wa + u), c);
        sc_c = c;
    }
    __syncthreads();

    if (tid < LL/16) {
        float m = sks[tid*16];
#pragma unroll
        for (int i = 1; i < 16; i++) m = fmaxf(m, sks[tid*16 + i]);
        cmax[tid] = m;
    }

    // superchunk sums from T8
    {
        int g = tid >> 7, d = tid & (DD-1);
#pragma unroll
        for (int q = g; q < NSC; q += 4) {
            float a0 = 0.f, a1 = 0.f;
#pragma unroll
            for (int j = 0; j < 8; j++) {
                a0 += g_T8 [(size_t)(b*NC + q*8 + j)*DD + d];
                a1 += g_T8e[(size_t)(b*NC + q*8 + j)*DD + d];
            }
            s8[0][q][d] = a0;
            s8[1][q][d] = a1;
        }
    }

    // Hillis-Steele inclusive scan of ek (9 steps)
    int cur = 0;
#pragma unroll
    for (int off = 1; off < LL; off <<= 1) {
        __syncthreads();
        float v = scan[cur][tid];
        if (tid >= off) v += scan[cur][tid - off];
        scan[cur ^ 1][tid] = v;
        cur ^= 1;
    }
    __syncthreads();

    // exclusive superchunk offsets (incl. total at [8]) -> global
    if (tid < DD) {
        int d = tid;
        float r0 = 0.f, r1 = 0.f;
#pragma unroll
        for (int sc = 0; sc < NSC; sc++) {
            g_SO0[(size_t)(b*(NSC+1) + sc)*DD + d] = r0;
            g_SO1[(size_t)(b*(NSC+1) + sc)*DD + d] = r1;
            r0 += s8[0][sc][d];
            r1 += s8[1][sc][d];
        }
        g_SO0[(size_t)(b*(NSC+1) + NSC)*DD + d] = r0;
        g_SO1[(size_t)(b*(NSC+1) + NSC)*DD + d] = r1;
    }

    // per-query softmax scalars
    {
        int t  = tid;
        int lo = max(0, t - 63);
        int hi = min(LL - 1, t + 64);
        int wc = hi - lo + 1;

        float wm = -INFINITY;
        int c0 = lo >> 4, c1 = hi >> 4;
        int e0 = (c0 + 1) << 4;
        for (int s = lo; s < e0; s++) wm = fmaxf(wm, sks[s]);
        for (int c = c0 + 1; c < c1; c++) wm = fmaxf(wm, cmax[c]);
        for (int s = c1 << 4; s <= hi; s++) wm = fmaxf(wm, sks[s]);

        float qc = g_qs[b*LL + t] + sc_c;
        float m  = fmaxf(0.f, qc + wm);     // masked entries score 0, always present
        float A  = expf(qc - m);
        float E  = expf(-m);
        float S1 = scan[cur][hi] - (lo > 0 ? scan[cur][lo-1] : 0.f);
        float Z  = A * S1 + E * (float)(LL - wc) + EPSF;
        float iv = 1.f / Z;
        g_A[b*LL + t] = A * iv;
        g_E[b*LL + t] = E * iv;
    }
}

// ---------------------------------------------------------------------------
// K3f: fused window-sum + output, fully preloaded; 4 queries/block with an
//      8-aligned anchor t8 (masked pre-slides). grid=1024, blk=128
// ---------------------------------------------------------------------------
__global__ __launch_bounds__(128)
void k3f(const float* __restrict__ x, float* __restrict__ out) {
    int blk = blockIdx.x;                // 0..1023
    int b   = blk >> 7;
    int t0  = (blk & 127) * 4;           // first query of this block
    int t8  = t0 & ~7;                   // 8-aligned anchor
    int pre = t0 - t8;                   // 0 or 4 pre-slides
    int d   = threadIdx.x;

    bool lo_act = (t8 >= 64);    // else window bottom pinned at 0 for t8..t8+7
    bool hi_act = (t8 <= 440);   // else window top pinned at 511 for t8..t8+7
    float whi = hi_act ? 1.f : 0.f;
    float wlo = lo_act ? 1.f : 0.f;

    int jh = hi_act ? ((t8 >> 3) + 8) : NC;   // chunk index of anchor window top
    int jl = lo_act ? ((t8 >> 3) - 8) : 0;    // chunk index of anchor window bottom
    int sc_h = jh >> 3, r_h = jh & 7;
    int sc_l = jl >> 3, r_l = jl & 7;

    const float* xb  = x + (size_t)b * LL * DD;
    const float* ekb = g_ek + b*LL;
    size_t sobase = (size_t)b * (NSC+1) * DD;
    size_t t8base = (size_t)b * NC;

    // ---- issue ALL loads up front (independent; predicated T8 hops) ----
    float c0h = __ldg(g_SO0 + sobase + (size_t)sc_h*DD + d);
    float c1h = __ldg(g_SO1 + sobase + (size_t)sc_h*DD + d);
    float c0l = __ldg(g_SO0 + sobase + (size_t)sc_l*DD + d);
    float c1l = __ldg(g_SO1 + sobase + (size_t)sc_l*DD + d);
    float tot = __ldg(g_SO0 + sobase + (size_t)NSC*DD + d);

#pragma unroll
    for (int j = 0; j < 7; j++) {
        if (j < r_h) {
            c0h += __ldg(g_T8  + (size_t)(t8base + sc_h*8 + j)*DD + d);
            c1h += __ldg(g_T8e + (size_t)(t8base + sc_h*8 + j)*DD + d);
        }
        if (j < r_l) {
            c0l += __ldg(g_T8  + (size_t)(t8base + sc_l*8 + j)*DD + d);
            c1l += __ldg(g_T8e + (size_t)(t8base + sc_l*8 + j)*DD + d);
        }
    }

    float xh[8], eh[8], xl[8], el[8], Ar[4], Er[4];
#pragma unroll
    for (int i = 0; i < 8; i++) {
        int th = min(t8 + 64 + i, LL - 1);          // clamped: always valid
        int tl = max(t8 - 64 + i, 0);
        xh[i] = __ldg(xb + (size_t)th*DD + d);
        xl[i] = __ldg(xb + (size_t)tl*DD + d);
        eh[i] = __ldg(ekb + th) * whi;              // masked weight
        el[i] = __ldg(ekb + tl) * wlo;
    }
#pragma unroll
    for (int i = 0; i < 4; i++) {
        Ar[i] = __ldg(g_A + b*LL + t0 + i);
        Er[i] = __ldg(g_E + b*LL + t0 + i);
    }

    // ---- pure register compute: slide from anchor, emit queries t0..t0+3 ----
    float V0 = c0h - c0l;
    float V1 = c1h - c1l;
    float* ob = out + ((size_t)b*LL + t0)*DD + d;

    if (pre == 0) {
#pragma unroll
        for (int i = 0; i < 4; i++) {
            V0 = fmaf( whi, xh[i], V0);
            V1 = fmaf(eh[i], xh[i], V1);
            V0 = fmaf(-wlo, xl[i], V0);
            V1 = fmaf(-el[i], xl[i], V1);
            ob[(size_t)i*DD] = Ar[i]*V1 + Er[i]*(tot - V0);
        }
    } else {
#pragma unroll
        for (int i = 0; i < 8; i++) {
            V0 = fmaf( whi, xh[i], V0);
            V1 = fmaf(eh[i], xh[i], V1);
            V0 = fmaf(-wlo, xl[i], V0);
            V1 = fmaf(-el[i], xl[i], V1);
            if (i >= 4)
                ob[(size_t)(i-4)*DD] = Ar[i-4]*V1 + Er[i-4]*(tot - V0);
        }
    }
}

extern "C" void kernel_launch(void* const* d_in, const int* in_sizes, int n_in,
                              void* d_out, int out_size) {
    const float* x  = (const float*)d_in[0];   // [B,L,D]
    const float* Wt = (const float*)d_in[1];   // [D,U]
    const float* Wx = (const float*)d_in[2];   // [D,U]
    const float* bh = (const float*)d_in[3];   // [U]
    const float* Wa = (const float*)d_in[4];   // [U,1]
    const float* ba = (const float*)d_in[5];   // [1]
    float* out = (float*)d_out;                // [B,L,D]

    k1<<<BB*LL/8, 256>>>(x, Wt, Wx, Wa);
    k2<<<BB, 512>>>(bh, Wa, ba);
    k3f<<<BB*LL/4, DD>>>(x, out);
}

// round 15
// speedup vs baseline: 1.0151x; 1.0151x over previous
#include <cuda_runtime.h>
#include <math.h>

#define BB 8
#define LL 512
#define DD 128
#define UU 32
#define EPSF 1e-7f
#define NC 64            // 8-row chunks per batch
#define NSC 8            // superchunks of 64 rows per batch

// scratch (no allocs allowed) — 16B aligned for float2/float4 access
__device__ __align__(16) float g_qs[BB*LL];
__device__ __align__(16) float g_ks[BB*LL];
__device__ __align__(16) float g_ek[BB*LL];
__device__ __align__(16) float g_T8 [BB*NC*DD];       // 8-row sums of x
__device__ __align__(16) float g_T8e[BB*NC*DD];       // 8-row sums of ek*x
__device__ __align__(16) float g_SO0[BB*(NSC+1)*DD];  // superchunk offsets of x; [8]=total
__device__ __align__(16) float g_SO1[BB*(NSC+1)*DD];  // superchunk offsets of ek*x
__device__ __align__(16) float g_A[BB*LL];            // exp(qc-m)/Z
__device__ __align__(16) float g_E[BB*LL];            // exp(-m)/Z

__device__ __forceinline__ float2 ldg2(const float* p) {
    return __ldg(reinterpret_cast<const float2*>(p));
}

// ---------------------------------------------------------------------------
// K1: 16 tokens/block, 2 tokens/warp (2x ILP). Register weight fold
//     (width-8 shfl reduce). grid=256, blk=256
// ---------------------------------------------------------------------------
__global__ __launch_bounds__(256)
void k1(const float* __restrict__ x,
        const float* __restrict__ Wt, const float* __restrict__ Wx,
        const float* __restrict__ Wa) {
    int tid  = threadIdx.x;
    int warp = tid >> 5;
    int lane = tid & 31;
    int tok0 = blockIdx.x * 16 + warp * 2;      // warp handles tok0, tok0+1

    __shared__ __align__(16) float swt[DD], swx[DD];
    __shared__ __align__(16) float srow[16*DD];
    __shared__ float sek[16];

    // issue both x loads first (independent, long latency)
    float4 xv0 = __ldg(reinterpret_cast<const float4*>(x + (size_t)tok0 * DD) + lane);
    float4 xv1 = __ldg(reinterpret_cast<const float4*>(x + (size_t)(tok0+1) * DD) + lane);
    reinterpret_cast<float4*>(srow)[(warp*2  )*32 + lane] = xv0;
    reinterpret_cast<float4*>(srow)[(warp*2+1)*32 + lane] = xv1;

    // register fold: ug = tid&7 fixed; row(i) = (tid + 256*i) >> 3
    {
        int ug = tid & 7;
        float4 wa = __ldg(reinterpret_cast<const float4*>(Wa) + ug);
        const float4* Wt4 = reinterpret_cast<const float4*>(Wt);
        const float4* Wx4 = reinterpret_cast<const float4*>(Wx);
#pragma unroll
        for (int i = 0; i < 4; i++) {
            int idx = tid + i*256;
            int row = idx >> 3;
            float4 vt = __ldg(Wt4 + idx);
            float4 vx = __ldg(Wx4 + idx);
            float pt = vt.x*wa.x + vt.y*wa.y + vt.z*wa.z + vt.w*wa.w;
            float px = vx.x*wa.x + vx.y*wa.y + vx.z*wa.z + vx.w*wa.w;
#pragma unroll
            for (int o = 4; o; o >>= 1) {       // reduce across 8-lane row group
                pt += __shfl_down_sync(0xFFFFFFFFu, pt, o, 8);
                px += __shfl_down_sync(0xFFFFFFFFu, px, o, 8);
            }
            if (ug == 0) { swt[row] = pt; swx[row] = px; }
        }
    }
    __syncthreads();

    float4 wt = reinterpret_cast<const float4*>(swt)[lane];
    float4 wx = reinterpret_cast<const float4*>(swx)[lane];
    float q0 = xv0.x*wt.x + xv0.y*wt.y + xv0.z*wt.z + xv0.w*wt.w;
    float k0 = xv0.x*wx.x + xv0.y*wx.y + xv0.z*wx.z + xv0.w*wx.w;
    float q1 = xv1.x*wt.x + xv1.y*wt.y + xv1.z*wt.z + xv1.w*wt.w;
    float k1v = xv1.x*wx.x + xv1.y*wx.y + xv1.z*wx.z + xv1.w*wx.w;
#pragma unroll
    for (int o = 16; o; o >>= 1) {              // dual reduction, 4-way ILP
        q0  += __shfl_down_sync(0xFFFFFFFFu, q0,  o);
        k0  += __shfl_down_sync(0xFFFFFFFFu, k0,  o);
        q1  += __shfl_down_sync(0xFFFFFFFFu, q1,  o);
        k1v += __shfl_down_sync(0xFFFFFFFFu, k1v, o);
    }
    if (lane == 0) {
        float e0 = expf(k0), e1 = expf(k1v);
        g_qs[tok0]   = q0;  g_ks[tok0]   = k0;  g_ek[tok0]   = e0;
        g_qs[tok0+1] = q1;  g_ks[tok0+1] = k1v; g_ek[tok0+1] = e1;
        sek[warp*2]   = e0;
        sek[warp*2+1] = e1;
    }
    __syncthreads();

    // chunk-8 sums: thread group c (0/1) handles local tokens c*8..c*8+7
    {
        int c = tid >> 7;
        int d = tid & (DD-1);
        float s0 = 0.f, s1 = 0.f;
#pragma unroll
        for (int w = 0; w < 8; w++) {
            float v = srow[(c*8 + w)*DD + d];
            s0 += v;
            s1 = fmaf(sek[c*8 + w], v, s1);
        }
        size_t o = (size_t)(blockIdx.x*2 + c) * DD + d;   // global chunk index
        g_T8 [o] = s0;
        g_T8e[o] = s1;
    }
}

// ---------------------------------------------------------------------------
// K2: per-batch: scan(ek) + window max + A/E scalars + superchunk offsets SO.
//     grid=8, blk=512  (unchanged, proven)
// ---------------------------------------------------------------------------
__global__ __launch_bounds__(512, 1)
void k2(const float* __restrict__ bh, const float* __restrict__ Wa,
        const float* __restrict__ ba) {
    int b   = blockIdx.x;
    int tid = threadIdx.x;

    __shared__ float sks[LL];
    __shared__ float scan[2][LL];
    __shared__ float cmax[LL/16];
    __shared__ float s8[2][NSC][DD];
    __shared__ float sc_c;

    sks[tid]     = g_ks[b*LL + tid];
    scan[0][tid] = g_ek[b*LL + tid];
    if (tid == 0) {
        float c = __ldg(ba);
#pragma unroll
        for (int u = 0; u < UU; u++) c = fmaf(__ldg(bh + u), __ldg(Wa + u), c);
        sc_c = c;
    }
    __syncthreads();

    if (tid < LL/16) {
        float m = sks[tid*16];
#pragma unroll
        for (int i = 1; i < 16; i++) m = fmaxf(m, sks[tid*16 + i]);
        cmax[tid] = m;
    }

    // superchunk sums from T8
    {
        int g = tid >> 7, d = tid & (DD-1);
#pragma unroll
        for (int q = g; q < NSC; q += 4) {
            float a0 = 0.f, a1 = 0.f;
#pragma unroll
            for (int j = 0; j < 8; j++) {
                a0 += g_T8 [(size_t)(b*NC + q*8 + j)*DD + d];
                a1 += g_T8e[(size_t)(b*NC + q*8 + j)*DD + d];
            }
            s8[0][q][d] = a0;
            s8[1][q][d] = a1;
        }
    }

    // Hillis-Steele inclusive scan of ek (9 steps)
    int cur = 0;
#pragma unroll
    for (int off = 1; off < LL; off <<= 1) {
        __syncthreads();
        float v = scan[cur][tid];
        if (tid >= off) v += scan[cur][tid - off];
        scan[cur ^ 1][tid] = v;
        cur ^= 1;
    }
    __syncthreads();

    // exclusive superchunk offsets (incl. total at [8]) -> global
    if (tid < DD) {
        int d = tid;
        float r0 = 0.f, r1 = 0.f;
#pragma unroll
        for (int sc = 0; sc < NSC; sc++) {
            g_SO0[(size_t)(b*(NSC+1) + sc)*DD + d] = r0;
            g_SO1[(size_t)(b*(NSC+1) + sc)*DD + d] = r1;
            r0 += s8[0][sc][d];
            r1 += s8[1][sc][d];
        }
        g_SO0[(size_t)(b*(NSC+1) + NSC)*DD + d] = r0;
        g_SO1[(size_t)(b*(NSC+1) + NSC)*DD + d] = r1;
    }

    // per-query softmax scalars
    {
        int t  = tid;
        int lo = max(0, t - 63);
        int hi = min(LL - 1, t + 64);
        int wc = hi - lo + 1;

        float wm = -INFINITY;
        int c0 = lo >> 4, c1 = hi >> 4;
        int e0 = (c0 + 1) << 4;
        for (int s = lo; s < e0; s++) wm = fmaxf(wm, sks[s]);
        for (int c = c0 + 1; c < c1; c++) wm = fmaxf(wm, cmax[c]);
        for (int s = c1 << 4; s <= hi; s++) wm = fmaxf(wm, sks[s]);

        float qc = g_qs[b*LL + t] + sc_c;
        float m  = fmaxf(0.f, qc + wm);     // masked entries score 0, always present
        float A  = expf(qc - m);
        float E  = expf(-m);
        float S1 = scan[cur][hi] - (lo > 0 ? scan[cur][lo-1] : 0.f);
        float Z  = A * S1 + E * (float)(LL - wc) + EPSF;
        float iv = 1.f / Z;
        g_A[b*LL + t] = A * iv;
        g_E[b*LL + t] = E * iv;
    }
}

// ---------------------------------------------------------------------------
// K3f: float2 per thread, 16 queries/block in two 8-aligned groups;
//      uniform scalars staged via smem. grid=256, blk=128
// ---------------------------------------------------------------------------
__global__ __launch_bounds__(128)
void k3f(const float* __restrict__ x, float* __restrict__ out) {
    int blk = blockIdx.x;                // 0..255
    int b   = blk >> 5;
    int t0  = (blk & 31) * 16;
    int tid = threadIdx.x;
    int g   = tid >> 6;                  // query group 0/1 (warp-uniform)
    int d2  = tid & 63;
    int d   = d2 * 2;
    int t8  = t0 + g*8;                  // 8-aligned anchor of this group

    // sS[g][j]: j<8: ek at hi-edges; 8..15: ek at lo-edges; 16..23: A; 24..31: E
    __shared__ float sS[2][32];

    const float* ekb = g_ek + b*LL;
    if (tid < 64) {
        int gg = tid >> 5;
        int j  = tid & 31;
        int tt = t0 + gg*8;
        int kind = j >> 3, i = j & 7;
        float v;
        if      (kind == 0) v = __ldg(ekb + min(tt + 64 + i, LL-1));
        else if (kind == 1) v = __ldg(ekb + max(tt - 64 + i, 0));
        else if (kind == 2) v = __ldg(g_A + b*LL + tt + i);
        else                v = __ldg(g_E + b*LL + tt + i);
        sS[gg][j] = v;
    }

    bool lo_act = (t8 >= 64);
    bool hi_act = (t8 <= 440);
    float whi = hi_act ? 1.f : 0.f;
    float wlo = lo_act ? 1.f : 0.f;

    int jh = hi_act ? ((t8 >> 3) + 8) : NC;
    int jl = lo_act ? ((t8 >> 3) - 8) : 0;
    int sc_h = jh >> 3, r_h = jh & 7;
    int sc_l = jl >> 3, r_l = jl & 7;

    const float* xb = x + (size_t)b * LL * DD;
    size_t sobase = (size_t)b * (NSC+1) * DD + d;
    size_t t8base = (size_t)b * NC;

    // ---- issue ALL vector loads up front (independent; predicated T8 hops) ----
    float2 c0h = ldg2(g_SO0 + sobase + (size_t)sc_h*DD);
    float2 c1h = ldg2(g_SO1 + sobase + (size_t)sc_h*DD);
    float2 c0l = ldg2(g_SO0 + sobase + (size_t)sc_l*DD);
    float2 c1l = ldg2(g_SO1 + sobase + (size_t)sc_l*DD);
    float2 tot = ldg2(g_SO0 + sobase + (size_t)NSC*DD);

#pragma unroll
    for (int j = 0; j < 7; j++) {
        if (j < r_h) {
            float2 a = ldg2(g_T8  + (size_t)(t8base + sc_h*8 + j)*DD + d);
            float2 e = ldg2(g_T8e + (size_t)(t8base + sc_h*8 + j)*DD + d);
            c0h.x += a.x; c0h.y += a.y;
            c1h.x += e.x; c1h.y += e.y;
        }
        if (j < r_l) {
            float2 a = ldg2(g_T8  + (size_t)(t8base + sc_l*8 + j)*DD + d);
            float2 e = ldg2(g_T8e + (size_t)(t8base + sc_l*8 + j)*DD + d);
            c0l.x += a.x; c0l.y += a.y;
            c1l.x += e.x; c1l.y += e.y;
        }
    }

    float2 xh[8], xl[8];
#pragma unroll
    for (int i = 0; i < 8; i++) {
        int th = min(t8 + 64 + i, LL - 1);          // clamped: always valid
        int tl = max(t8 - 64 + i, 0);
        xh[i] = ldg2(xb + (size_t)th*DD + d);
        xl[i] = ldg2(xb + (size_t)tl*DD + d);
    }

    __syncthreads();   // sS ready

    // ---- compute: slide from anchor, emit 8 queries (float2 each) ----
    float2 V0, V1;
    V0.x = c0h.x - c0l.x;  V0.y = c0h.y - c0l.y;
    V1.x = c1h.x - c1l.x;  V1.y = c1h.y - c1l.y;

    float* ob = out + ((size_t)b*LL + t8)*DD + d;

#pragma unroll
    for (int i = 0; i < 8; i++) {
        float eh = sS[g][i]      * whi;
        float el = sS[g][8 + i]  * wlo;
        float A  = sS[g][16 + i];
        float E  = sS[g][24 + i];

        V0.x = fmaf( whi, xh[i].x, V0.x);  V0.y = fmaf( whi, xh[i].y, V0.y);
        V1.x = fmaf(  eh, xh[i].x, V1.x);  V1.y = fmaf(  eh, xh[i].y, V1.y);
        V0.x = fmaf(-wlo, xl[i].x, V0.x);  V0.y = fmaf(-wlo, xl[i].y, V0.y);
        V1.x = fmaf( -el, xl[i].x, V1.x);  V1.y = fmaf( -el, xl[i].y, V1.y);

        float2 o;
        o.x = A*V1.x + E*(tot.x - V0.x);
        o.y = A*V1.y + E*(tot.y - V0.y);
        *reinterpret_cast<float2*>(ob + (size_t)i*DD) = o;
    }
}

extern "C" void kernel_launch(void* const* d_in, const int* in_sizes, int n_in,
                              void* d_out, int out_size) {
    const float* x  = (const float*)d_in[0];   // [B,L,D]
    const float* Wt = (const float*)d_in[1];   // [D,U]
    const float* Wx = (const float*)d_in[2];   // [D,U]
    const float* bh = (const float*)d_in[3];   // [U]
    const float* Wa = (const float*)d_in[4];   // [U,1]
    const float* ba = (const float*)d_in[5];   // [1]
    float* out = (float*)d_out;                // [B,L,D]

    k1<<<BB*LL/16, 256>>>(x, Wt, Wx, Wa);
    k2<<<BB, 512>>>(bh, Wa, ba);
    k3f<<<BB*LL/16, 128>>>(x, out);
}

// round 16
// speedup vs baseline: 1.1572x; 1.1400x over previous
#include <cuda_runtime.h>
#include <math.h>

#define BB 8
#define LL 512
#define DD 128
#define UU 32
#define EPSF 1e-7f
#define NC 64            // 8-row chunks per batch

// scratch (no allocs allowed) — 16B aligned
__device__ __align__(16) float g_qs[BB*LL];
__device__ __align__(16) float g_ks[BB*LL];
__device__ __align__(16) float g_ek[BB*LL];
__device__ __align__(16) float g_T8 [BB*NC*DD];       // 8-row sums of x
__device__ __align__(16) float g_T8e[BB*NC*DD];       // 8-row sums of ek*x

__device__ __forceinline__ float2 ldg2(const float* p) {
    return __ldg(reinterpret_cast<const float2*>(p));
}

// ---------------------------------------------------------------------------
// kA: 16 tokens/block, 2 tokens/warp. Register weight fold (width-8 shfl).
//     grid=256, blk=256   (unchanged from R15 — proven)
// ---------------------------------------------------------------------------
__global__ __launch_bounds__(256)
void kA(const float* __restrict__ x,
        const float* __restrict__ Wt, const float* __restrict__ Wx,
        const float* __restrict__ Wa) {
    int tid  = threadIdx.x;
    int warp = tid >> 5;
    int lane = tid & 31;
    int tok0 = blockIdx.x * 16 + warp * 2;

    __shared__ __align__(16) float swt[DD], swx[DD];
    __shared__ __align__(16) float srow[16*DD];
    __shared__ float sek[16];

    float4 xv0 = __ldg(reinterpret_cast<const float4*>(x + (size_t)tok0 * DD) + lane);
    float4 xv1 = __ldg(reinterpret_cast<const float4*>(x + (size_t)(tok0+1) * DD) + lane);
    reinterpret_cast<float4*>(srow)[(warp*2  )*32 + lane] = xv0;
    reinterpret_cast<float4*>(srow)[(warp*2+1)*32 + lane] = xv1;

    {
        int ug = tid & 7;
        float4 wa = __ldg(reinterpret_cast<const float4*>(Wa) + ug);
        const float4* Wt4 = reinterpret_cast<const float4*>(Wt);
        const float4* Wx4 = reinterpret_cast<const float4*>(Wx);
#pragma unroll
        for (int i = 0; i < 4; i++) {
            int idx = tid + i*256;
            int row = idx >> 3;
            float4 vt = __ldg(Wt4 + idx);
            float4 vx = __ldg(Wx4 + idx);
            float pt = vt.x*wa.x + vt.y*wa.y + vt.z*wa.z + vt.w*wa.w;
            float px = vx.x*wa.x + vx.y*wa.y + vx.z*wa.z + vx.w*wa.w;
#pragma unroll
            for (int o = 4; o; o >>= 1) {
                pt += __shfl_down_sync(0xFFFFFFFFu, pt, o, 8);
                px += __shfl_down_sync(0xFFFFFFFFu, px, o, 8);
            }
            if (ug == 0) { swt[row] = pt; swx[row] = px; }
        }
    }
    __syncthreads();

    float4 wt = reinterpret_cast<const float4*>(swt)[lane];
    float4 wx = reinterpret_cast<const float4*>(swx)[lane];
    float q0 = xv0.x*wt.x + xv0.y*wt.y + xv0.z*wt.z + xv0.w*wt.w;
    float k0 = xv0.x*wx.x + xv0.y*wx.y + xv0.z*wx.z + xv0.w*wx.w;
    float q1 = xv1.x*wt.x + xv1.y*wt.y + xv1.z*wt.z + xv1.w*wt.w;
    float k1v = xv1.x*wx.x + xv1.y*wx.y + xv1.z*wx.z + xv1.w*wx.w;
#pragma unroll
    for (int o = 16; o; o >>= 1) {
        q0  += __shfl_down_sync(0xFFFFFFFFu, q0,  o);
        k0  += __shfl_down_sync(0xFFFFFFFFu, k0,  o);
        q1  += __shfl_down_sync(0xFFFFFFFFu, q1,  o);
        k1v += __shfl_down_sync(0xFFFFFFFFu, k1v, o);
    }
    if (lane == 0) {
        float e0 = expf(k0), e1 = expf(k1v);
        g_qs[tok0]   = q0;  g_ks[tok0]   = k0;  g_ek[tok0]   = e0;
        g_qs[tok0+1] = q1;  g_ks[tok0+1] = k1v; g_ek[tok0+1] = e1;
        sek[warp*2]   = e0;
        sek[warp*2+1] = e1;
    }
    __syncthreads();

    {
        int c = tid >> 7;
        int d = tid & (DD-1);
        float s0 = 0.f, s1 = 0.f;
#pragma unroll
        for (int w = 0; w < 8; w++) {
            float v = srow[(c*8 + w)*DD + d];
            s0 += v;
            s1 = fmaf(sek[c*8 + w], v, s1);
        }
        size_t o = (size_t)(blockIdx.x*2 + c) * DD + d;
        g_T8 [o] = s0;
        g_T8e[o] = s1;
    }
}

// ---------------------------------------------------------------------------
// kB: fused softmax-scalars + window-sum + output. 16 queries/block,
//     float2 per thread, two 8-aligned groups. grid=256, blk=128.
//     A/E computed in-block (replaces k2); window sums straight from T8.
// ---------------------------------------------------------------------------
__global__ __launch_bounds__(128)
void kB(const float* __restrict__ x,
        const float* __restrict__ bh, const float* __restrict__ Wa,
        const float* __restrict__ ba, float* __restrict__ out) {
    int blk = blockIdx.x;                // 0..255
    int b   = blk >> 5;
    int t0  = (blk & 31) * 16;
    int tid = threadIdx.x;
    int g   = tid >> 6;                  // query group 0/1
    int d2  = tid & 63;
    int d   = d2 * 2;
    int t8  = t0 + g*8;                  // 8-aligned anchor of this group

    __shared__ __align__(16) float sek[LL], sks[LL];
    __shared__ float2 sTot[2][64];
    __shared__ float m16[LL/16], s16[LL/16];
    __shared__ float sA[16], sE[16], sqs[16];
    __shared__ float sc;

    // ---- stage ek/ks for this batch (L2-broadcast; 32 blocks share) ----
    reinterpret_cast<float4*>(sek)[tid] =
        __ldg(reinterpret_cast<const float4*>(g_ek + b*LL) + tid);
    reinterpret_cast<float4*>(sks)[tid] =
        __ldg(reinterpret_cast<const float4*>(g_ks + b*LL) + tid);
    if (tid < 16) sqs[tid] = __ldg(g_qs + b*LL + t0 + tid);
    if (tid == 16) {
        float c = __ldg(ba);
#pragma unroll
        for (int u = 0; u < UU; u++) c = fmaf(__ldg(bh + u), __ldg(Wa + u), c);
        sc = c;
    }

    // ---- tot partials: each thread sums 32 chunks (its half) for its d pair ----
    size_t t8base = (size_t)b * NC;
    {
        float2 p = make_float2(0.f, 0.f);
#pragma unroll
        for (int j = 0; j < 32; j++) {
            float2 a = ldg2(g_T8 + (size_t)(t8base + g*32 + j)*DD + d);
            p.x += a.x; p.y += a.y;
        }
        sTot[g][d2] = p;
    }

    // ---- window chunk sums (registers, predicated; <=16 chunks) ----
    bool lo_act = (t8 >= 64);
    bool hi_act = (t8 <= 440);
    float whi = hi_act ? 1.f : 0.f;
    float wlo = lo_act ? 1.f : 0.f;
    int jh = hi_act ? ((t8 >> 3) + 8) : NC;
    int jl = lo_act ? ((t8 >> 3) - 8) : 0;

    float2 V0 = make_float2(0.f, 0.f), V1 = make_float2(0.f, 0.f);
#pragma unroll
    for (int j = 0; j < 16; j++) {
        int idx = jl + j;
        if (idx < jh) {
            float2 a = ldg2(g_T8  + (size_t)(t8base + idx)*DD + d);
            float2 e = ldg2(g_T8e + (size_t)(t8base + idx)*DD + d);
            V0.x += a.x; V0.y += a.y;
            V1.x += e.x; V1.y += e.y;
        }
    }

    // ---- edge x rows (independent) ----
    const float* xb = x + (size_t)b * LL * DD;
    float2 xh[8], xl[8];
#pragma unroll
    for (int i = 0; i < 8; i++) {
        int th = min(t8 + 64 + i, LL - 1);
        int tl = max(t8 - 64 + i, 0);
        xh[i] = ldg2(xb + (size_t)th*DD + d);
        xl[i] = ldg2(xb + (size_t)tl*DD + d);
    }

    __syncthreads();   // sek/sks/sqs/sc staged; sTot partials written

    // ---- 16-group max/sum partials (threads 0-31) ----
    if (tid < 32) {
        float m = sks[tid*16], s = sek[tid*16];
#pragma unroll
        for (int i = 1; i < 16; i++) {
            m = fmaxf(m, sks[tid*16 + i]);
            s += sek[tid*16 + i];
        }
        m16[tid] = m;
        s16[tid] = s;
    }
    __syncthreads();

    // ---- per-query softmax scalars (threads 0-15), exactly as k2 ----
    if (tid < 16) {
        int t  = t0 + tid;
        int lo = max(0, t - 63);
        int hi = min(LL - 1, t + 64);
        int wc = hi - lo + 1;

        float wm = -INFINITY, S1 = 0.f;
        int c0 = lo >> 4, c1 = hi >> 4;
        int e0 = (c0 + 1) << 4;
        for (int s = lo; s < e0; s++)      { wm = fmaxf(wm, sks[s]); S1 += sek[s]; }
        for (int c = c0 + 1; c < c1; c++)  { wm = fmaxf(wm, m16[c]); S1 += s16[c]; }
        for (int s = c1 << 4; s <= hi; s++){ wm = fmaxf(wm, sks[s]); S1 += sek[s]; }

        float qc = sqs[tid] + sc;
        float m  = fmaxf(0.f, qc + wm);     // masked entries score 0, always present
        float A  = expf(qc - m);
        float E  = expf(-m);
        float Z  = A * S1 + E * (float)(LL - wc) + EPSF;
        float iv = 1.f / Z;
        sA[tid] = A * iv;
        sE[tid] = E * iv;
    }
    __syncthreads();

    float2 tp0 = sTot[0][d2], tp1 = sTot[1][d2];
    float2 tot = make_float2(tp0.x + tp1.x, tp0.y + tp1.y);

    // ---- slides + emit (ek edges from smem; clamped indices, masked) ----
    float* ob = out + ((size_t)b*LL + t8)*DD + d;
#pragma unroll
    for (int i = 0; i < 8; i++) {
        float eh = sek[min(t8 + 64 + i, LL - 1)] * whi;
        float el = sek[max(t8 - 64 + i, 0)]      * wlo;
        int q = g*8 + i;
        float A = sA[q], E = sE[q];

        V0.x = fmaf( whi, xh[i].x, V0.x);  V0.y = fmaf( whi, xh[i].y, V0.y);
        V1.x = fmaf(  eh, xh[i].x, V1.x);  V1.y = fmaf(  eh, xh[i].y, V1.y);
        V0.x = fmaf(-wlo, xl[i].x, V0.x);  V0.y = fmaf(-wlo, xl[i].y, V0.y);
        V1.x = fmaf( -el, xl[i].x, V1.x);  V1.y = fmaf( -el, xl[i].y, V1.y);

        float2 o;
        o.x = A*V1.x + E*(tot.x - V0.x);
        o.y = A*V1.y + E*(tot.y - V0.y);
        *reinterpret_cast<float2*>(ob + (size_t)i*DD) = o;
    }
}

extern "C" void kernel_launch(void* const* d_in, const int* in_sizes, int n_in,
                              void* d_out, int out_size) {
    const float* x  = (const float*)d_in[0];   // [B,L,D]
    const float* Wt = (const float*)d_in[1];   // [D,U]
    const float* Wx = (const float*)d_in[2];   // [D,U]
    const float* bh = (const float*)d_in[3];   // [U]
    const float* Wa = (const float*)d_in[4];   // [U,1]
    const float* ba = (const float*)d_in[5];   // [1]
    float* out = (float*)d_out;                // [B,L,D]

    kA<<<BB*LL/16, 256>>>(x, Wt, Wx, Wa);
    kB<<<BB*LL/16, 128>>>(x, bh, Wa, ba, out);
}

// round 17
// speedup vs baseline: 1.1775x; 1.0175x over previous
#include <cuda_runtime.h>
#include <math.h>

#define BB 8
#define LL 512
#define DD 128
#define UU 32
#define EPSF 1e-7f
#define NC 64            // 8-row chunks per batch

// scratch (no allocs allowed) — 16B aligned
__device__ __align__(16) float g_qs[BB*LL];
__device__ __align__(16) float g_ks[BB*LL];
__device__ __align__(16) float g_ek[BB*LL];
__device__ __align__(16) float g_T8 [BB*NC*DD];       // 8-row sums of x
__device__ __align__(16) float g_T8e[BB*NC*DD];       // 8-row sums of ek*x

__device__ __forceinline__ float2 ldg2(const float* p) {
    return __ldg(reinterpret_cast<const float2*>(p));
}

// ---------------------------------------------------------------------------
// kA: 16 tokens/block, 2 tokens/warp. Register weight fold (width-8 shfl).
//     grid=256, blk=256   (unchanged — proven)
// ---------------------------------------------------------------------------
__global__ __launch_bounds__(256)
void kA(const float* __restrict__ x,
        const float* __restrict__ Wt, const float* __restrict__ Wx,
        const float* __restrict__ Wa) {
    int tid  = threadIdx.x;
    int warp = tid >> 5;
    int lane = tid & 31;
    int tok0 = blockIdx.x * 16 + warp * 2;

    __shared__ __align__(16) float swt[DD], swx[DD];
    __shared__ __align__(16) float srow[16*DD];
    __shared__ float sek[16];

    float4 xv0 = __ldg(reinterpret_cast<const float4*>(x + (size_t)tok0 * DD) + lane);
    float4 xv1 = __ldg(reinterpret_cast<const float4*>(x + (size_t)(tok0+1) * DD) + lane);
    reinterpret_cast<float4*>(srow)[(warp*2  )*32 + lane] = xv0;
    reinterpret_cast<float4*>(srow)[(warp*2+1)*32 + lane] = xv1;

    {
        int ug = tid & 7;
        float4 wa = __ldg(reinterpret_cast<const float4*>(Wa) + ug);
        const float4* Wt4 = reinterpret_cast<const float4*>(Wt);
        const float4* Wx4 = reinterpret_cast<const float4*>(Wx);
#pragma unroll
        for (int i = 0; i < 4; i++) {
            int idx = tid + i*256;
            int row = idx >> 3;
            float4 vt = __ldg(Wt4 + idx);
            float4 vx = __ldg(Wx4 + idx);
            float pt = vt.x*wa.x + vt.y*wa.y + vt.z*wa.z + vt.w*wa.w;
            float px = vx.x*wa.x + vx.y*wa.y + vx.z*wa.z + vx.w*wa.w;
#pragma unroll
            for (int o = 4; o; o >>= 1) {
                pt += __shfl_down_sync(0xFFFFFFFFu, pt, o, 8);
                px += __shfl_down_sync(0xFFFFFFFFu, px, o, 8);
            }
            if (ug == 0) { swt[row] = pt; swx[row] = px; }
        }
    }
    __syncthreads();

    float4 wt = reinterpret_cast<const float4*>(swt)[lane];
    float4 wx = reinterpret_cast<const float4*>(swx)[lane];
    float q0 = xv0.x*wt.x + xv0.y*wt.y + xv0.z*wt.z + xv0.w*wt.w;
    float k0 = xv0.x*wx.x + xv0.y*wx.y + xv0.z*wx.z + xv0.w*wx.w;
    float q1 = xv1.x*wt.x + xv1.y*wt.y + xv1.z*wt.z + xv1.w*wt.w;
    float k1v = xv1.x*wx.x + xv1.y*wx.y + xv1.z*wx.z + xv1.w*wx.w;
#pragma unroll
    for (int o = 16; o; o >>= 1) {
        q0  += __shfl_down_sync(0xFFFFFFFFu, q0,  o);
        k0  += __shfl_down_sync(0xFFFFFFFFu, k0,  o);
        q1  += __shfl_down_sync(0xFFFFFFFFu, q1,  o);
        k1v += __shfl_down_sync(0xFFFFFFFFu, k1v, o);
    }
    if (lane == 0) {
        float e0 = expf(k0), e1 = expf(k1v);
        g_qs[tok0]   = q0;  g_ks[tok0]   = k0;  g_ek[tok0]   = e0;
        g_qs[tok0+1] = q1;  g_ks[tok0+1] = k1v; g_ek[tok0+1] = e1;
        sek[warp*2]   = e0;
        sek[warp*2+1] = e1;
    }
    __syncthreads();

    {
        int c = tid >> 7;
        int d = tid & (DD-1);
        float s0 = 0.f, s1 = 0.f;
#pragma unroll
        for (int w = 0; w < 8; w++) {
            float v = srow[(c*8 + w)*DD + d];
            s0 += v;
            s1 = fmaf(sek[c*8 + w], v, s1);
        }
        size_t o = (size_t)(blockIdx.x*2 + c) * DD + d;
        g_T8 [o] = s0;
        g_T8e[o] = s1;
    }
}

// ---------------------------------------------------------------------------
// kB: fused softmax-scalars + window-sum + output. 16 queries/block in FOUR
//     4-query groups (8-aligned anchor, masked pre-slides), 256 threads,
//     float2 per thread. grid=256.
// ---------------------------------------------------------------------------
__global__ __launch_bounds__(256)
void kB(const float* __restrict__ x,
        const float* __restrict__ bh, const float* __restrict__ Wa,
        const float* __restrict__ ba, float* __restrict__ out) {
    int blk = blockIdx.x;                // 0..255
    int b   = blk >> 5;
    int t0  = (blk & 31) * 16;
    int tid = threadIdx.x;
    int g   = tid >> 6;                  // query subgroup 0..3 (4 queries each)
    int d2  = tid & 63;
    int d   = d2 * 2;
    int tq  = t0 + g*4;                  // first query of subgroup
    int t8  = t0 + (g >> 1)*8;           // 8-aligned anchor
    int pre = (g & 1) * 4;               // 0 or 4 pre-slides

    __shared__ __align__(16) float sek[LL], sks[LL];
    __shared__ float2 sTot[4][64];
    __shared__ float m16[LL/16], s16[LL/16];
    __shared__ float sA[16], sE[16], sqs[16];
    __shared__ float sc;

    // ---- stage ek/ks (one float4 per thread; L2-broadcast across 32 blocks) ----
    if (tid < 128)
        reinterpret_cast<float4*>(sek)[tid] =
            __ldg(reinterpret_cast<const float4*>(g_ek + b*LL) + tid);
    else
        reinterpret_cast<float4*>(sks)[tid-128] =
            __ldg(reinterpret_cast<const float4*>(g_ks + b*LL) + (tid-128));
    if (tid < 16) sqs[tid] = __ldg(g_qs + b*LL + t0 + tid);
    if (tid == 16) {
        float c = __ldg(ba);
#pragma unroll
        for (int u = 0; u < UU; u++) c = fmaf(__ldg(bh + u), __ldg(Wa + u), c);
        sc = c;
    }

    // ---- tot partials: each thread sums 16 chunks for its d pair ----
    size_t t8base = (size_t)b * NC;
    {
        float2 p = make_float2(0.f, 0.f);
#pragma unroll
        for (int j = 0; j < 16; j++) {
            float2 a = ldg2(g_T8 + (size_t)(t8base + g*16 + j)*DD + d);
            p.x += a.x; p.y += a.y;
        }
        sTot[g][d2] = p;
    }

    // ---- window chunk sums for the anchor (registers, predicated) ----
    bool lo_act = (t8 >= 64);
    bool hi_act = (t8 <= 440);
    float whi = hi_act ? 1.f : 0.f;
    float wlo = lo_act ? 1.f : 0.f;
    int jh = hi_act ? ((t8 >> 3) + 8) : NC;
    int jl = lo_act ? ((t8 >> 3) - 8) : 0;

    float2 V0 = make_float2(0.f, 0.f), V1 = make_float2(0.f, 0.f);
#pragma unroll
    for (int j = 0; j < 16; j++) {
        int idx = jl + j;
        if (idx < jh) {
            float2 a = ldg2(g_T8  + (size_t)(t8base + idx)*DD + d);
            float2 e = ldg2(g_T8e + (size_t)(t8base + idx)*DD + d);
            V0.x += a.x; V0.y += a.y;
            V1.x += e.x; V1.y += e.y;
        }
    }

    // ---- edge x rows: only pre+4 slides needed (warp-uniform predicate) ----
    const float* xb = x + (size_t)b * LL * DD;
    int nsl = pre + 4;
    float2 xh[8], xl[8];
#pragma unroll
    for (int i = 0; i < 8; i++) {
        if (i < nsl) {
            int th = min(t8 + 64 + i, LL - 1);
            int tl = max(t8 - 64 + i, 0);
            xh[i] = ldg2(xb + (size_t)th*DD + d);
            xl[i] = ldg2(xb + (size_t)tl*DD + d);
        }
    }

    __syncthreads();   // staging + sTot partials complete

    // ---- 16-group max/sum partials (threads 0-31) ----
    if (tid < 32) {
        float m = sks[tid*16], s = sek[tid*16];
#pragma unroll
        for (int i = 1; i < 16; i++) {
            m = fmaxf(m, sks[tid*16 + i]);
            s += sek[tid*16 + i];
        }
        m16[tid] = m;
        s16[tid] = s;
    }
    __syncthreads();

    // ---- per-query softmax scalars (threads 0-15) ----
    if (tid < 16) {
        int t  = t0 + tid;
        int lo = max(0, t - 63);
        int hi = min(LL - 1, t + 64);
        int wc = hi - lo + 1;

        float wm = -INFINITY, S1 = 0.f;
        int c0 = lo >> 4, c1 = hi >> 4;
        int e0 = (c0 + 1) << 4;
        for (int s = lo; s < e0; s++)      { wm = fmaxf(wm, sks[s]); S1 += sek[s]; }
        for (int c = c0 + 1; c < c1; c++)  { wm = fmaxf(wm, m16[c]); S1 += s16[c]; }
        for (int s = c1 << 4; s <= hi; s++){ wm = fmaxf(wm, sks[s]); S1 += sek[s]; }

        float qc = sqs[tid] + sc;
        float m  = fmaxf(0.f, qc + wm);     // masked entries score 0, always present
        float A  = expf(qc - m);
        float E  = expf(-m);
        float Z  = A * S1 + E * (float)(LL - wc) + EPSF;
        float iv = 1.f / Z;
        sA[tid] = A * iv;
        sE[tid] = E * iv;
    }
    __syncthreads();

    float2 tot;
    {
        float2 a = sTot[0][d2], bb2 = sTot[1][d2], c = sTot[2][d2], dd = sTot[3][d2];
        tot = make_float2(a.x + bb2.x + c.x + dd.x, a.y + bb2.y + c.y + dd.y);
    }

    // ---- slides + emit 4 queries (i in [pre, pre+4)) ----
    float* ob = out + ((size_t)b*LL + tq)*DD + d;
#pragma unroll
    for (int i = 0; i < 8; i++) {
        if (i < nsl) {
            float eh = sek[min(t8 + 64 + i, LL - 1)] * whi;
            float el = sek[max(t8 - 64 + i, 0)]      * wlo;

            V0.x = fmaf( whi, xh[i].x, V0.x);  V0.y = fmaf( whi, xh[i].y, V0.y);
            V1.x = fmaf(  eh, xh[i].x, V1.x);  V1.y = fmaf(  eh, xh[i].y, V1.y);
            V0.x = fmaf(-wlo, xl[i].x, V0.x);  V0.y = fmaf(-wlo, xl[i].y, V0.y);
            V1.x = fmaf( -el, xl[i].x, V1.x);  V1.y = fmaf( -el, xl[i].y, V1.y);

            if (i >= pre) {
                int q = (t8 + i) - t0;           // local query index 0..15
                float A = sA[q], E = sE[q];
                float2 o;
                o.x = A*V1.x + E*(tot.x - V0.x);
                o.y = A*V1.y + E*(tot.y - V0.y);
                *reinterpret_cast<float2*>(ob + (size_t)(i - pre)*DD) = o;
            }
        }
    }
}

extern "C" void kernel_launch(void* const* d_in, const int* in_sizes, int n_in,
                              void* d_out, int out_size) {
    const float* x  = (const float*)d_in[0];   // [B,L,D]
    const float* Wt = (const float*)d_in[1];   // [D,U]
    const float* Wx = (const float*)d_in[2];   // [D,U]
    const float* bh = (const float*)d_in[3];   // [U]
    const float* Wa = (const float*)d_in[4];   // [U,1]
    const float* ba = (const float*)d_in[5];   // [1]
    float* out = (float*)d_out;                // [B,L,D]

    kA<<<BB*LL/16, 256>>>(x, Wt, Wx, Wa);
    kB<<<BB*LL/16, 256>>>(x, bh, Wa, ba, out);
}